// round 16
// baseline (speedup 1.0000x reference)
#include <cuda_runtime.h>
#include <cstdint>

#define MG 4096
#define DD 128
#define K_BLOCKS 912   // 6 blocks/SM x 152 SMs

// device scratch — no allocation
__device__ int g_start[MG + 1];
__device__ unsigned int g_counter;

__device__ __forceinline__ void f4add(float4& a, const float4& v) {
    a.x += v.x; a.y += v.y; a.z += v.z; a.w += v.w;
}

// LDG float4 with L2 cache-hint policy (evict_last): allocates + retains in L2.
__device__ __forceinline__ float4 ldg_pol(const float4* p, unsigned long long pol) {
    float4 v;
    asm("ld.global.nc.L2::cache_hint.v4.f32 {%0,%1,%2,%3}, [%4], %5;"
        : "=f"(v.x), "=f"(v.y), "=f"(v.z), "=f"(v.w)
        : "l"(p), "l"(pol));
    return v;
}

// K0: segment start table from sorted seg (int4 per thread) + counter reset.
__global__ void k0_starts(const int* __restrict__ seg, int N) {
    int t = blockIdx.x * blockDim.x + threadIdx.x;
    if (t == 0) g_counter = 0;
    int base = t * 4;
    if (base >= N) return;

    int4 v = *reinterpret_cast<const int4*>(seg + base);   // N % 4 == 0
    int prev = (base == 0) ? -1 : __ldg(seg + base - 1);

    int e[4] = {v.x, v.y, v.z, v.w};
    #pragma unroll
    for (int k = 0; k < 4; ++k) {
        int cur = e[k];
        if (cur != prev) {
            for (int s = prev + 1; s <= cur; ++s) g_start[s] = base + k;
        }
        prev = cur;
    }
    if (base + 4 >= N) {
        for (int s = prev + 1; s <= MG; ++s) g_start[s] = N;
    }
}

// Fused kernel, LDG-based. Per stolen segment m:
//   (a) sum phase: direct LDG (evict_last) accumulation, 4-deep batched
//   (b) tree reduce + GEMV epilogue -> vn_out[m], y in smem
//   (c) broadcast: out_h[row] = h[row] + y, re-reading h from L2
//       in REVERSE tile order (most recently loaded tiles first).
// __launch_bounds__(256, 6): cap regs at 42 so 6 blocks/SM are resident.
__global__ void __launch_bounds__(256, 6) k_fused(const float* __restrict__ h,
                                                  const float* __restrict__ vn_h,
                                                  const float* __restrict__ W,
                                                  const float* __restrict__ bias,
                                                  float* __restrict__ vn_out,
                                                  float* __restrict__ out_h) {
    __shared__ float4 sred[8][32];                // tree-reduction scratch
    __shared__ __align__(16) float xv[DD];        // x = vn_h[m] + pool
    __shared__ __align__(16) float part[DD];      // GEMV partials
    __shared__ __align__(16) float yv[DD];        // y = vn_new[m]
    __shared__ int sm_next;

    const int tid = threadIdx.x;
    const int c   = tid & 31;    // float4 chunk in row
    const int rl  = tid >> 5;    // row lane

    unsigned long long pol;
    asm("createpolicy.fractional.L2::evict_last.b64 %0, 1.0;" : "=l"(pol));

    const float4* h4 = reinterpret_cast<const float4*>(h);
    float4* out4     = reinterpret_cast<float4*>(out_h);

    for (;;) {
        if (tid == 0) sm_next = (int)atomicAdd(&g_counter, 1u);
        __syncthreads();
        const int m = sm_next;
        if (m >= MG) break;

        const int start = g_start[m];
        const int end   = g_start[m + 1];

        // ---- (a) sum phase: direct LDG, evict_last, 4-deep batched ----
        float4 a0 = make_float4(0.f, 0.f, 0.f, 0.f);
        float4 a1 = make_float4(0.f, 0.f, 0.f, 0.f);
        {
            int row = start + rl;
            for (; row + 24 < end; row += 32) {
                float4 v0 = ldg_pol(h4 + (size_t)(row)      * 32 + c, pol);
                float4 v1 = ldg_pol(h4 + (size_t)(row + 8)  * 32 + c, pol);
                float4 v2 = ldg_pol(h4 + (size_t)(row + 16) * 32 + c, pol);
                float4 v3 = ldg_pol(h4 + (size_t)(row + 24) * 32 + c, pol);
                f4add(a0, v0); f4add(a1, v1); f4add(a0, v2); f4add(a1, v3);
            }
            for (; row < end; row += 8) {
                float4 v = ldg_pol(h4 + (size_t)row * 32 + c, pol);
                f4add(a0, v);
            }
        }

        // ---- tree reduce 8 lanes -> xv = pool + vn_h[m] ----
        f4add(a0, a1);
        sred[rl][c] = a0;
        __syncthreads();
        if (rl < 4) { f4add(a0, sred[rl + 4][c]); sred[rl][c] = a0; }
        __syncthreads();
        if (rl < 2) { f4add(a0, sred[rl + 2][c]); sred[rl][c] = a0; }
        __syncthreads();
        if (rl == 0) {
            f4add(a0, sred[1][c]);
            float4 vh = *reinterpret_cast<const float4*>(vn_h + (size_t)m * DD + 4 * c);
            f4add(a0, vh);
            *reinterpret_cast<float4*>(&xv[4 * c]) = a0;
        }
        __syncthreads();

        // ---- (b) GEMV epilogue: 2 threads per output row j ----
        {
            const int j    = tid >> 1;
            const int half = tid & 1;
            const float4* Wr = reinterpret_cast<const float4*>(W + (size_t)j * DD + half * 64);
            const float* xp0 = &xv[half * 64];
            float s = 0.f;
            #pragma unroll
            for (int k4 = 0; k4 < 16; ++k4) {
                float4 w = Wr[k4];
                const float* xp = xp0 + k4 * 4;
                s += xp[0] * w.x + xp[1] * w.y + xp[2] * w.z + xp[3] * w.w;
            }
            if (half) part[j] = s;
            __syncthreads();
            if (!half) {
                float t = s + part[j] + bias[j];
                t = t > 0.f ? t : 0.f;
                float y = vn_h[(size_t)m * DD + j] + t;
                yv[j] = y;
                vn_out[(size_t)m * DD + j] = y;
            }
        }
        __syncthreads();   // yv visible

        // ---- (c) broadcast phase, REVERSE tile order (LIFO L2 reuse) ----
        {
            const float4 y4 = *reinterpret_cast<const float4*>(&yv[4 * c]);
            const int nrows = end - start;
            const int n32 = (nrows + 31) >> 5;
            for (int t32 = n32 - 1; t32 >= 0; --t32) {
                const int r0 = start + (t32 << 5);
                const int rows_this = (end - r0 < 32) ? (end - r0) : 32;
                if (rows_this == 32) {
                    const int row = r0 + rl;
                    float4 v0 = __ldcs(h4 + (size_t)(row)      * 32 + c);
                    float4 v1 = __ldcs(h4 + (size_t)(row + 8)  * 32 + c);
                    float4 v2 = __ldcs(h4 + (size_t)(row + 16) * 32 + c);
                    float4 v3 = __ldcs(h4 + (size_t)(row + 24) * 32 + c);
                    f4add(v0, y4); f4add(v1, y4); f4add(v2, y4); f4add(v3, y4);
                    __stcs(out4 + (size_t)(row)      * 32 + c, v0);
                    __stcs(out4 + (size_t)(row + 8)  * 32 + c, v1);
                    __stcs(out4 + (size_t)(row + 16) * 32 + c, v2);
                    __stcs(out4 + (size_t)(row + 24) * 32 + c, v3);
                } else {
                    for (int row = r0 + rl; row < end; row += 8) {
                        float4 v = __ldcs(h4 + (size_t)row * 32 + c);
                        f4add(v, y4);
                        __stcs(out4 + (size_t)row * 32 + c, v);
                    }
                }
            }
        }
        __syncthreads();   // protect smem before next stolen segment
    }
}

extern "C" void kernel_launch(void* const* d_in, const int* in_sizes, int n_in,
                              void* d_out, int out_size) {
    const float* h    = (const float*)d_in[0];      // [N, 128]
    const float* vn_h = (const float*)d_in[1];      // [4096, 128]
    const int*   seg  = (const int*)d_in[2];        // [N] sorted int32
    const float* W    = (const float*)d_in[3];      // [128, 128]
    const float* b    = (const float*)d_in[4];      // [128]

    const int N = in_sizes[0] / DD;                   // 1,000,000
    float* out_h  = (float*)d_out;                    // h_new [N,128]
    float* out_vn = (float*)d_out + (size_t)N * DD;   // vn_h_new [4096,128]

    // K0: segment start table + counter reset
    int k0_threads = (N + 3) / 4;
    k0_starts<<<(k0_threads + 255) / 256, 256>>>(seg, N);

    // Fused sum + vn-update + broadcast (persistent work-stealing, 6/SM)
    k_fused<<<K_BLOCKS, 256>>>(h, vn_h, W, b, out_vn, out_h);
}

// round 17
// speedup vs baseline: 1.2550x; 1.2550x over previous
#include <cuda_runtime.h>
#include <cstdint>

#define MG 4096
#define DD 128
#define K_BLOCKS 608

// device scratch — no allocation
__device__ int g_start[MG + 1];
__device__ unsigned int g_counter;

__device__ __forceinline__ void f4add(float4& a, const float4& v) {
    a.x += v.x; a.y += v.y; a.z += v.z; a.w += v.w;
}

// LDG float4 with L2 cache-hint policy (evict_last): allocates + retains in L2.
__device__ __forceinline__ float4 ldg_pol(const float4* p, unsigned long long pol) {
    float4 v;
    asm("ld.global.nc.L2::cache_hint.v4.f32 {%0,%1,%2,%3}, [%4], %5;"
        : "=f"(v.x), "=f"(v.y), "=f"(v.z), "=f"(v.w)
        : "l"(p), "l"(pol));
    return v;
}

// K0: segment start table from sorted seg (int4 per thread) + counter reset.
__global__ void k0_starts(const int* __restrict__ seg, int N) {
    int t = blockIdx.x * blockDim.x + threadIdx.x;
    if (t == 0) g_counter = 0;
    int base = t * 4;
    if (base >= N) return;

    int4 v = *reinterpret_cast<const int4*>(seg + base);   // N % 4 == 0
    int prev = (base == 0) ? -1 : __ldg(seg + base - 1);

    int e[4] = {v.x, v.y, v.z, v.w};
    #pragma unroll
    for (int k = 0; k < 4; ++k) {
        int cur = e[k];
        if (cur != prev) {
            for (int s = prev + 1; s <= cur; ++s) g_start[s] = base + k;
        }
        prev = cur;
    }
    if (base + 4 >= N) {
        for (int s = prev + 1; s <= MG; ++s) g_start[s] = N;
    }
}

// Fused kernel, LDG-based. Per stolen segment m:
//   (a) sum phase: direct LDG (evict_last), EIGHT loads in flight per thread
//   (b) tree reduce + GEMV epilogue -> vn_out[m], y in smem
//   (c) broadcast: out_h[row] = h[row] + y, re-reading h from L2
//       in REVERSE tile order (most recently loaded tiles first).
// NO launch_bounds reg cap: spills destroy load batching (measured R16).
__global__ void __launch_bounds__(256) k_fused(const float* __restrict__ h,
                                               const float* __restrict__ vn_h,
                                               const float* __restrict__ W,
                                               const float* __restrict__ bias,
                                               float* __restrict__ vn_out,
                                               float* __restrict__ out_h) {
    __shared__ float4 sred[8][32];                // tree-reduction scratch
    __shared__ __align__(16) float xv[DD];        // x = vn_h[m] + pool
    __shared__ __align__(16) float part[DD];      // GEMV partials
    __shared__ __align__(16) float yv[DD];        // y = vn_new[m]
    __shared__ int sm_next;

    const int tid = threadIdx.x;
    const int c   = tid & 31;    // float4 chunk in row
    const int rl  = tid >> 5;    // row lane

    unsigned long long pol;
    asm("createpolicy.fractional.L2::evict_last.b64 %0, 1.0;" : "=l"(pol));

    const float4* h4 = reinterpret_cast<const float4*>(h);
    float4* out4     = reinterpret_cast<float4*>(out_h);

    for (;;) {
        if (tid == 0) sm_next = (int)atomicAdd(&g_counter, 1u);
        __syncthreads();
        const int m = sm_next;
        if (m >= MG) break;

        const int start = g_start[m];
        const int end   = g_start[m + 1];

        // ---- (a) sum phase: direct LDG, evict_last, 8-deep batched ----
        float4 a0 = make_float4(0.f, 0.f, 0.f, 0.f);
        float4 a1 = make_float4(0.f, 0.f, 0.f, 0.f);
        float4 a2 = make_float4(0.f, 0.f, 0.f, 0.f);
        float4 a3 = make_float4(0.f, 0.f, 0.f, 0.f);
        {
            int row = start + rl;
            // main: 64 rows per block-iteration, 8 loads in flight per thread
            for (; row + 56 < end; row += 64) {
                float4 v0 = ldg_pol(h4 + (size_t)(row)      * 32 + c, pol);
                float4 v1 = ldg_pol(h4 + (size_t)(row + 8)  * 32 + c, pol);
                float4 v2 = ldg_pol(h4 + (size_t)(row + 16) * 32 + c, pol);
                float4 v3 = ldg_pol(h4 + (size_t)(row + 24) * 32 + c, pol);
                float4 v4 = ldg_pol(h4 + (size_t)(row + 32) * 32 + c, pol);
                float4 v5 = ldg_pol(h4 + (size_t)(row + 40) * 32 + c, pol);
                float4 v6 = ldg_pol(h4 + (size_t)(row + 48) * 32 + c, pol);
                float4 v7 = ldg_pol(h4 + (size_t)(row + 56) * 32 + c, pol);
                f4add(a0, v0); f4add(a1, v1); f4add(a2, v2); f4add(a3, v3);
                f4add(a0, v4); f4add(a1, v5); f4add(a2, v6); f4add(a3, v7);
            }
            for (; row < end; row += 8) {
                float4 v = ldg_pol(h4 + (size_t)row * 32 + c, pol);
                f4add(a0, v);
            }
        }

        // ---- tree reduce 8 lanes -> xv = pool + vn_h[m] ----
        f4add(a0, a1); f4add(a2, a3); f4add(a0, a2);
        sred[rl][c] = a0;
        __syncthreads();
        if (rl < 4) { f4add(a0, sred[rl + 4][c]); sred[rl][c] = a0; }
        __syncthreads();
        if (rl < 2) { f4add(a0, sred[rl + 2][c]); sred[rl][c] = a0; }
        __syncthreads();
        if (rl == 0) {
            f4add(a0, sred[1][c]);
            float4 vh = *reinterpret_cast<const float4*>(vn_h + (size_t)m * DD + 4 * c);
            f4add(a0, vh);
            *reinterpret_cast<float4*>(&xv[4 * c]) = a0;
        }
        __syncthreads();

        // ---- (b) GEMV epilogue: 2 threads per output row j ----
        {
            const int j    = tid >> 1;
            const int half = tid & 1;
            const float4* Wr = reinterpret_cast<const float4*>(W + (size_t)j * DD + half * 64);
            const float* xp0 = &xv[half * 64];
            float s = 0.f;
            #pragma unroll
            for (int k4 = 0; k4 < 16; ++k4) {
                float4 w = Wr[k4];
                const float* xp = xp0 + k4 * 4;
                s += xp[0] * w.x + xp[1] * w.y + xp[2] * w.z + xp[3] * w.w;
            }
            if (half) part[j] = s;
            __syncthreads();
            if (!half) {
                float t = s + part[j] + bias[j];
                t = t > 0.f ? t : 0.f;
                float y = vn_h[(size_t)m * DD + j] + t;
                yv[j] = y;
                vn_out[(size_t)m * DD + j] = y;
            }
        }
        __syncthreads();   // yv visible

        // ---- (c) broadcast phase, REVERSE tile order (LIFO L2 reuse) ----
        {
            const float4 y4 = *reinterpret_cast<const float4*>(&yv[4 * c]);
            const int nrows = end - start;
            const int n32 = (nrows + 31) >> 5;
            for (int t32 = n32 - 1; t32 >= 0; --t32) {
                const int r0 = start + (t32 << 5);
                const int rows_this = (end - r0 < 32) ? (end - r0) : 32;
                if (rows_this == 32) {
                    const int row = r0 + rl;
                    float4 v0 = __ldcs(h4 + (size_t)(row)      * 32 + c);
                    float4 v1 = __ldcs(h4 + (size_t)(row + 8)  * 32 + c);
                    float4 v2 = __ldcs(h4 + (size_t)(row + 16) * 32 + c);
                    float4 v3 = __ldcs(h4 + (size_t)(row + 24) * 32 + c);
                    f4add(v0, y4); f4add(v1, y4); f4add(v2, y4); f4add(v3, y4);
                    __stcs(out4 + (size_t)(row)      * 32 + c, v0);
                    __stcs(out4 + (size_t)(row + 8)  * 32 + c, v1);
                    __stcs(out4 + (size_t)(row + 16) * 32 + c, v2);
                    __stcs(out4 + (size_t)(row + 24) * 32 + c, v3);
                } else {
                    for (int row = r0 + rl; row < end; row += 8) {
                        float4 v = __ldcs(h4 + (size_t)row * 32 + c);
                        f4add(v, y4);
                        __stcs(out4 + (size_t)row * 32 + c, v);
                    }
                }
            }
        }
        __syncthreads();   // protect smem before next stolen segment
    }
}

extern "C" void kernel_launch(void* const* d_in, const int* in_sizes, int n_in,
                              void* d_out, int out_size) {
    const float* h    = (const float*)d_in[0];      // [N, 128]
    const float* vn_h = (const float*)d_in[1];      // [4096, 128]
    const int*   seg  = (const int*)d_in[2];        // [N] sorted int32
    const float* W    = (const float*)d_in[3];      // [128, 128]
    const float* b    = (const float*)d_in[4];      // [128]

    const int N = in_sizes[0] / DD;                   // 1,000,000
    float* out_h  = (float*)d_out;                    // h_new [N,128]
    float* out_vn = (float*)d_out + (size_t)N * DD;   // vn_h_new [4096,128]

    // K0: segment start table + counter reset
    int k0_threads = (N + 3) / 4;
    k0_starts<<<(k0_threads + 255) / 256, 256>>>(seg, N);

    // Fused sum + vn-update + broadcast (persistent work-stealing)
    k_fused<<<K_BLOCKS, 256>>>(h, vn_h, W, b, out_vn, out_h);
}